// round 8
// baseline (speedup 1.0000x reference)
#include <cuda_runtime.h>
#include <cuda_bf16.h>
#include <cstdint>

// Problem shape (fixed by the dataset)
#define B 64
#define S 512
#define DD 512

#define NEG_ORD ((int)0xB19194D7)   // ordf(-1e9f)
#define NEGF (-1e9f)

// ---------------- global scratch (no allocations allowed) ----------------
__device__ __align__(16) __nv_bfloat16 g_A_hi[(size_t)B * S * DD];
__device__ __align__(16) __nv_bfloat16 g_A_lo[(size_t)B * S * DD];
__device__ __align__(16) __nv_bfloat16 g_B_hi[(size_t)B * S * DD];
__device__ __align__(16) __nv_bfloat16 g_B_lo[(size_t)B * S * DD];
__device__ int g_rowmax[B * S];
__device__ int g_colmax[B * S];

// ---------------- helpers ----------------
__device__ __forceinline__ int ordf(float f) {
    int i = __float_as_int(f);
    return (i >= 0) ? i : (i ^ 0x7FFFFFFF);
}
__device__ __forceinline__ float deord(int s) {
    return __int_as_float((s >= 0) ? s : (s ^ 0x7FFFFFFF));
}
__device__ __forceinline__ uint32_t smem_u32(const void* p) {
    uint32_t a;
    asm("{ .reg .u64 t; cvta.to.shared.u64 t, %1; cvt.u32.u64 %0, t; }" : "=r"(a) : "l"(p));
    return a;
}

#define CP_ASYNC16(dst, src) \
    asm volatile("cp.async.cg.shared.global [%0], [%1], 16;" :: "r"(dst), "l"(src) : "memory")
#define CP_COMMIT()  asm volatile("cp.async.commit_group;" ::: "memory")
#define CP_WAIT(n)   asm volatile("cp.async.wait_group %0;" :: "n"(n) : "memory")

#define LDSM_X4(r0, r1, r2, r3, addr) \
    asm volatile("ldmatrix.sync.aligned.m8n8.x4.shared.b16 {%0,%1,%2,%3}, [%4];" \
                 : "=r"(r0), "=r"(r1), "=r"(r2), "=r"(r3) : "r"(addr))

#define MMA_BF16(c, a, b0v, b1v) \
    asm volatile("mma.sync.aligned.m16n8k16.row.col.f32.bf16.bf16.f32 " \
                 "{%0,%1,%2,%3}, {%4,%5,%6,%7}, {%8,%9}, {%0,%1,%2,%3};" \
                 : "+f"((c)[0]), "+f"((c)[1]), "+f"((c)[2]), "+f"((c)[3]) \
                 : "r"((a)[0]), "r"((a)[1]), "r"((a)[2]), "r"((a)[3]), "r"(b0v), "r"(b1v))

// ---------------- prep: normalize + bf16 hi/lo split ----------------
template <int SIDE>
__global__ void k_prep(const float* __restrict__ in) {
    int row  = (blockIdx.x * blockDim.x + threadIdx.x) >> 5;
    int lane = threadIdx.x & 31;
    if (row >= B * S) return;
    const float4* rp = (const float4*)(in + (size_t)row * DD);

    float4 v0a = rp[2 * lane],        v0b = rp[2 * lane + 1];
    float4 v1a = rp[2 * (lane + 32)], v1b = rp[2 * (lane + 32) + 1];

    float ss = 0.f;
    ss = fmaf(v0a.x, v0a.x, ss); ss = fmaf(v0a.y, v0a.y, ss);
    ss = fmaf(v0a.z, v0a.z, ss); ss = fmaf(v0a.w, v0a.w, ss);
    ss = fmaf(v0b.x, v0b.x, ss); ss = fmaf(v0b.y, v0b.y, ss);
    ss = fmaf(v0b.z, v0b.z, ss); ss = fmaf(v0b.w, v0b.w, ss);
    ss = fmaf(v1a.x, v1a.x, ss); ss = fmaf(v1a.y, v1a.y, ss);
    ss = fmaf(v1a.z, v1a.z, ss); ss = fmaf(v1a.w, v1a.w, ss);
    ss = fmaf(v1b.x, v1b.x, ss); ss = fmaf(v1b.y, v1b.y, ss);
    ss = fmaf(v1b.z, v1b.z, ss); ss = fmaf(v1b.w, v1b.w, ss);
#pragma unroll
    for (int o = 16; o > 0; o >>= 1) ss += __shfl_xor_sync(0xFFFFFFFFu, ss, o);
    float inv = 1.0f / fmaxf(sqrtf(ss), 1e-8f);

    __nv_bfloat16* dhi = (SIDE == 0) ? g_A_hi : g_B_hi;
    __nv_bfloat16* dlo = (SIDE == 0) ? g_A_lo : g_B_lo;
    if (lane == 0) {
        if (SIDE == 0) g_rowmax[row] = NEG_ORD; else g_colmax[row] = NEG_ORD;
    }

#pragma unroll
    for (int half = 0; half < 2; half++) {
        float x[8];
        if (half == 0) {
            x[0] = v0a.x; x[1] = v0a.y; x[2] = v0a.z; x[3] = v0a.w;
            x[4] = v0b.x; x[5] = v0b.y; x[6] = v0b.z; x[7] = v0b.w;
        } else {
            x[0] = v1a.x; x[1] = v1a.y; x[2] = v1a.z; x[3] = v1a.w;
            x[4] = v1b.x; x[5] = v1b.y; x[6] = v1b.z; x[7] = v1b.w;
        }
        __nv_bfloat16 h[8], l[8];
#pragma unroll
        for (int u = 0; u < 8; u++) {
            float v = x[u] * inv;
            h[u] = __float2bfloat16(v);
            l[u] = __float2bfloat16(v - __bfloat162float(h[u]));
        }
        size_t idx = (size_t)row * DD + (size_t)(lane + 32 * half) * 8;
        *(uint4*)(dhi + idx) = *(uint4*)h;
        *(uint4*)(dlo + idx) = *(uint4*)l;
    }
}

// ---------------- GEMM: bf16 mma.sync split-precision + masked row/col max ----------------
// CTA 256 threads (8 warps), tile 128(i) x 256(j), k-chunk 64, 2-stage cp.async pipeline.
// Warp grid 2(row) x 4(col): warp tile 64x64 = 4 m16-frags x 8 n8-frags.
// Split-precision terms per k16, ordered in 3 passes of 32 independent MMAs:
//   hh: Ahi*Bhi, lh: Alo*Bhi, hl: Ahi*Blo  (aux regs shared between Alo and Blo).
#define KCH 64
#define NCHUNK (DD / KCH)
#define TM 128
#define TN 256
#define STAGE_BYTES 98304
#define OFF_AHI 0
#define OFF_ALO 16384
#define OFF_BHI 32768
#define OFF_BLO 65536

__global__ __launch_bounds__(256, 1) void k_gemm(const int* __restrict__ mask1,
                                                 const int* __restrict__ mask2) {
    extern __shared__ __align__(1024) char smem[];
    __shared__ int m1s[TM], m2s[TN];

    const uint32_t sb = smem_u32(smem);
    const int tid  = threadIdx.x;
    const int wid  = tid >> 5;
    const int lane = tid & 31;
    const int b  = blockIdx.z;
    const int ib = blockIdx.y;
    const int jb = blockIdx.x;
    const int i0 = ib * TM;
    const int j0 = jb * TN;

    if (tid < TM) m1s[tid] = mask1[b * S + i0 + tid];
    m2s[tid] = mask2[b * S + j0 + tid];

    const __nv_bfloat16* pAhi = g_A_hi + ((size_t)b * S + i0) * DD;
    const __nv_bfloat16* pAlo = g_A_lo + ((size_t)b * S + i0) * DD;
    const __nv_bfloat16* pBhi = g_B_hi + ((size_t)b * S + j0) * DD;
    const __nv_bfloat16* pBlo = g_B_lo + ((size_t)b * S + j0) * DD;

    auto issue_chunk = [&](int kc, int st) {
        uint32_t stg = sb + st * STAGE_BYTES;
        size_t kbase = (size_t)kc * KCH;
        // A granules: 1024 (128 rows x 8), 4 per thread, hi+lo
#pragma unroll
        for (int u = 0; u < 4; u++) {
            int G = tid + 256 * u;
            int row = G >> 3, kg = G & 7;
            size_t so = (size_t)row * DD + kbase + kg * 8;
            uint32_t dd = (uint32_t)(row * 128 + ((kg ^ (row & 7)) * 16));
            CP_ASYNC16(stg + OFF_AHI + dd, pAhi + so);
            CP_ASYNC16(stg + OFF_ALO + dd, pAlo + so);
        }
        // B granules: 2048 (256 rows x 8), 8 per thread, hi+lo
#pragma unroll
        for (int u = 0; u < 8; u++) {
            int G = tid + 256 * u;
            int row = G >> 3, kg = G & 7;
            size_t so = (size_t)row * DD + kbase + kg * 8;
            uint32_t dd = (uint32_t)(row * 128 + ((kg ^ (row & 7)) * 16));
            CP_ASYNC16(stg + OFF_BHI + dd, pBhi + so);
            CP_ASYNC16(stg + OFF_BLO + dd, pBlo + so);
        }
    };

    float acc[4][8][4];
#pragma unroll
    for (int mi = 0; mi < 4; mi++)
#pragma unroll
        for (int nj = 0; nj < 8; nj++)
#pragma unroll
            for (int r = 0; r < 4; r++) acc[mi][nj][r] = 0.f;

    const int wr = (wid >> 2) * 64;   // 2 row groups
    const int wc = (wid & 3) * 64;    // 4 col groups

    // ldmatrix lane address components
    const int a_r = (lane & 7) + 8 * ((lane >> 3) & 1);
    const int a_k = lane >> 4;
    const int b_r = (lane & 7) + 8 * (lane >> 4);
    const int b_k = (lane >> 3) & 1;

    issue_chunk(0, 0);
    CP_COMMIT();

#pragma unroll 1
    for (int t = 0; t < NCHUNK; t++) {
        if (t < NCHUNK - 1) {
            issue_chunk(t + 1, (t + 1) & 1);
            CP_COMMIT();
            CP_WAIT(1);
        } else {
            CP_WAIT(0);
        }
        __syncthreads();

        uint32_t stg = sb + (t & 1) * STAGE_BYTES;
#pragma unroll
        for (int ks = 0; ks < 4; ks++) {
            const int kg0 = ks * 2;
            uint32_t ah[4][4], bh[4][4], aux[4][4];

            // A-hi and B-hi fragments
#pragma unroll
            for (int mi = 0; mi < 4; mi++) {
                int row = wr + 16 * mi + a_r;
                uint32_t ad = stg + (uint32_t)(row * 128 + (((kg0 + a_k) ^ (row & 7)) * 16));
                LDSM_X4(ah[mi][0], ah[mi][1], ah[mi][2], ah[mi][3], ad + OFF_AHI);
            }
#pragma unroll
            for (int nb = 0; nb < 4; nb++) {
                int row = wc + 16 * nb + b_r;
                uint32_t bd = stg + (uint32_t)(row * 128 + (((kg0 + b_k) ^ (row & 7)) * 16));
                LDSM_X4(bh[nb][0], bh[nb][1], bh[nb][2], bh[nb][3], bd + OFF_BHI);
            }

            // pass 1: hi * hi  (32 independent MMAs)
#pragma unroll
            for (int mi = 0; mi < 4; mi++)
#pragma unroll
                for (int nb = 0; nb < 4; nb++) {
                    MMA_BF16(acc[mi][2 * nb],     ah[mi], bh[nb][0], bh[nb][1]);
                    MMA_BF16(acc[mi][2 * nb + 1], ah[mi], bh[nb][2], bh[nb][3]);
                }

            // A-lo fragments into aux
#pragma unroll
            for (int mi = 0; mi < 4; mi++) {
                int row = wr + 16 * mi + a_r;
                uint32_t ad = stg + (uint32_t)(row * 128 + (((kg0 + a_k) ^ (row & 7)) * 16));
                LDSM_X4(aux[mi][0], aux[mi][1], aux[mi][2], aux[mi][3], ad + OFF_ALO);
            }
            // pass 2: lo * hi
#pragma unroll
            for (int mi = 0; mi < 4; mi++)
#pragma unroll
                for (int nb = 0; nb < 4; nb++) {
                    MMA_BF16(acc[mi][2 * nb],     aux[mi], bh[nb][0], bh[nb][1]);
                    MMA_BF16(acc[mi][2 * nb + 1], aux[mi], bh[nb][2], bh[nb][3]);
                }

            // B-lo fragments into aux
#pragma unroll
            for (int nb = 0; nb < 4; nb++) {
                int row = wc + 16 * nb + b_r;
                uint32_t bd = stg + (uint32_t)(row * 128 + (((kg0 + b_k) ^ (row & 7)) * 16));
                LDSM_X4(aux[nb][0], aux[nb][1], aux[nb][2], aux[nb][3], bd + OFF_BLO);
            }
            // pass 3: hi * lo
#pragma unroll
            for (int mi = 0; mi < 4; mi++)
#pragma unroll
                for (int nb = 0; nb < 4; nb++) {
                    MMA_BF16(acc[mi][2 * nb],     ah[mi], aux[nb][0], aux[nb][1]);
                    MMA_BF16(acc[mi][2 * nb + 1], ah[mi], aux[nb][2], aux[nb][3]);
                }
        }
        __syncthreads();
    }

    // -------- epilogue: masked row/col maxes from D fragments --------
    const int g  = lane >> 2;
    const int tg = lane & 3;

    int cmask[8][2];
#pragma unroll
    for (int nj = 0; nj < 8; nj++) {
        cmask[nj][0] = m2s[wc + 8 * nj + 2 * tg];
        cmask[nj][1] = m2s[wc + 8 * nj + 2 * tg + 1];
    }
    int rmask[4][2];
#pragma unroll
    for (int mi = 0; mi < 4; mi++) {
        rmask[mi][0] = m1s[wr + 16 * mi + g];
        rmask[mi][1] = m1s[wr + 16 * mi + g + 8];
    }

    // row maxes: reduce over tg lanes
#pragma unroll
    for (int mi = 0; mi < 4; mi++)
#pragma unroll
        for (int p = 0; p < 2; p++) {
            float rm = NEGF;
#pragma unroll
            for (int nj = 0; nj < 8; nj++) {
                if (cmask[nj][0]) rm = fmaxf(rm, acc[mi][nj][2 * p]);
                if (cmask[nj][1]) rm = fmaxf(rm, acc[mi][nj][2 * p + 1]);
            }
            rm = fmaxf(rm, __shfl_xor_sync(0xFFFFFFFFu, rm, 1));
            rm = fmaxf(rm, __shfl_xor_sync(0xFFFFFFFFu, rm, 2));
            if (tg == 0)
                atomicMax(&g_rowmax[b * S + i0 + wr + 16 * mi + g + 8 * p], ordf(rm));
        }

    // col maxes: reduce over g lanes
#pragma unroll
    for (int nj = 0; nj < 8; nj++)
#pragma unroll
        for (int q = 0; q < 2; q++) {
            float cm = NEGF;
#pragma unroll
            for (int mi = 0; mi < 4; mi++) {
                if (rmask[mi][0]) cm = fmaxf(cm, acc[mi][nj][q]);
                if (rmask[mi][1]) cm = fmaxf(cm, acc[mi][nj][2 + q]);
            }
            cm = fmaxf(cm, __shfl_xor_sync(0xFFFFFFFFu, cm, 4));
            cm = fmaxf(cm, __shfl_xor_sync(0xFFFFFFFFu, cm, 8));
            cm = fmaxf(cm, __shfl_xor_sync(0xFFFFFFFFu, cm, 16));
            if (g == 0)
                atomicMax(&g_colmax[b * S + j0 + wc + 8 * nj + 2 * tg + q], ordf(cm));
        }
}

// ---------------- final masked sums ----------------
__global__ void k_final(const int* __restrict__ mask1, const int* __restrict__ mask2,
                        float* __restrict__ out) {
    __shared__ float ssum[256];
    __shared__ int   scnt[256];
    const int b = blockIdx.x;
    const int tid = threadIdx.x;

    float s = 0.f;
    int   n = 0;
    for (int i = tid; i < S; i += 256) {
        int m1 = mask1[b * S + i];
        if (m1) s += deord(g_rowmax[b * S + i]);
        n += m1;
        int m2 = mask2[b * S + i];
        if (m2) s += deord(g_colmax[b * S + i]);
        n += m2;
    }
    ssum[tid] = s; scnt[tid] = n;
    __syncthreads();
    for (int o = 128; o > 0; o >>= 1) {
        if (tid < o) { ssum[tid] += ssum[tid + o]; scnt[tid] += scnt[tid + o]; }
        __syncthreads();
    }
    if (tid == 0) out[b] = ssum[0] / (float)scnt[0];
}

// ---------------- launch ----------------
extern "C" void kernel_launch(void* const* d_in, const int* in_sizes, int n_in,
                              void* d_out, int out_size) {
    const float* emb1  = (const float*)d_in[0];
    const float* emb2  = (const float*)d_in[1];
    const int*   mask1 = (const int*)d_in[2];
    const int*   mask2 = (const int*)d_in[3];
    float*       out   = (float*)d_out;

    static bool attr_set = false;
    if (!attr_set) {
        cudaFuncSetAttribute(k_gemm, cudaFuncAttributeMaxDynamicSharedMemorySize, 2 * STAGE_BYTES);
        attr_set = true;
    }

    // 1) prep (one warp per row)
    k_prep<0><<<(B * S) / 8, 256>>>(emb1);
    k_prep<1><<<(B * S) / 8, 256>>>(emb2);

    // 2) GEMM + masked maxes: grid (jb=2, ib=4, b=64) = 512 CTAs
    dim3 grid(S / TN, S / TM, B);
    k_gemm<<<grid, 256, 2 * STAGE_BYTES>>>(mask1, mask2);

    // 3) final
    k_final<<<B, 256>>>(mask1, mask2, out);
}